// round 3
// baseline (speedup 1.0000x reference)
#include <cuda_runtime.h>
#include <cstdint>

// ---------------------------------------------------------------------------
// Problem constants
//   B=2, L=4096 (64x64), D_MODEL=192, D_INNER=384, D_STATE=16, D_CONV=4,
//   DT_RANK=12, 4 scan directions -> N_SEQ = 8 sequences of length 4096.
// ---------------------------------------------------------------------------
#define LSEQ   4096
#define HW     64
#define DM     192
#define DI     384
#define DS     16
#define DTR    12
#define NSEQ   8
#define NTOK   8192           // B * L
#define NROWS  32768          // NSEQ * L
#define CH_T   64             // chunk length
#define CH_G   64             // number of chunks

// ---------------------------------------------------------------------------
// Scratch (device globals; no allocation allowed)
// ---------------------------------------------------------------------------
__device__ float g_P  [(size_t)NTOK  * 768];   // x @ in_proj_w  [b*t, 768]
__device__ float g_xcs[(size_t)NROWS * DI];    // silu(conv)     [n*t, 384]
__device__ float g_dbc[(size_t)NROWS * 44];    // xcs @ x_proj_w [n*t, 44]
__device__ float g_e1 [(size_t)NROWS * DI];    // exp(-dt)
__device__ float g_dtx[(size_t)NROWS * DI];    // dt * xcs
__device__ float g_hend[(size_t)NSEQ * CH_G * DS * DI];
__device__ float g_h0  [(size_t)NSEQ * CH_G * DS * DI];
__device__ float g_E  [(size_t)NSEQ * CH_G * DI];
__device__ float g_y  [(size_t)NROWS * DI];    // scan output per direction
__device__ float g_G  [(size_t)NTOK  * DI];    // (sum_dir y) * silu(z)
__device__ float g_O1 [(size_t)NTOK  * DM];    // G @ mamba_out_w
__device__ float g_N1 [(size_t)NTOK  * DM];    // LayerNorm(O1)

// ---------------------------------------------------------------------------
// Direction index map: sequence position t -> original token index
// t = p*64 + q
//   dir0: p*64+q       dir1: (63-q)*64+p
//   dir2: (63-p)*64+(63-q)    dir3: q*64+(63-p)
// ---------------------------------------------------------------------------
__device__ __forceinline__ int gmap(int dir, int t) {
    int p = t >> 6, q = t & 63;
    switch (dir) {
        case 0:  return t;
        case 1:  return ((63 - q) << 6) + p;
        case 2:  return ((63 - p) << 6) + (63 - q);
        default: return (q << 6) + (63 - p);
    }
}

// ---------------------------------------------------------------------------
// Generic tiled FP32 GEMM: C[M,N] = A[M,K] @ W[K,N]  (+ resid + bias)
// 64x64 tile, BK=16, 128 threads, 4x8 per-thread microtile.
// M % 64 == 0, K % 16 == 0 always hold here; N guarded by template.
// ---------------------------------------------------------------------------
template<bool NG, bool RESID>
__global__ __launch_bounds__(128)
void gemm64(const float* __restrict__ A, const float* __restrict__ W,
            float* __restrict__ C, int M, int N, int K,
            const float* __restrict__ resid, const float* __restrict__ bias)
{
    __shared__ __align__(16) float As[16][68];   // padded: conflict-free reads
    __shared__ __align__(16) float Bs[16][64];

    const int tid = threadIdx.x;
    const int tm = tid >> 3, tn = tid & 7;
    const int m0 = blockIdx.y * 64, n0 = blockIdx.x * 64;

    float acc[4][8];
#pragma unroll
    for (int i = 0; i < 4; i++)
#pragma unroll
        for (int j = 0; j < 8; j++) acc[i][j] = 0.f;

    for (int k0 = 0; k0 < K; k0 += 16) {
#pragma unroll
        for (int e = 0; e < 8; e++) {               // A tile: 1024 elems
            int l = e * 128 + tid;
            int r = l >> 4, kk = l & 15;
            As[kk][r] = A[(size_t)(m0 + r) * K + k0 + kk];
        }
#pragma unroll
        for (int e = 0; e < 8; e++) {               // W tile
            int l = e * 128 + tid;
            int kk = l >> 6, c = l & 63;
            float w = 0.f;
            if (!NG || (n0 + c) < N) w = W[(size_t)(k0 + kk) * N + n0 + c];
            Bs[kk][c] = w;
        }
        __syncthreads();
#pragma unroll
        for (int kk = 0; kk < 16; kk++) {
            float4 av = *reinterpret_cast<const float4*>(&As[kk][tm * 4]);
            float4 b0 = *reinterpret_cast<const float4*>(&Bs[kk][tn * 8]);
            float4 b1 = *reinterpret_cast<const float4*>(&Bs[kk][tn * 8 + 4]);
            float a[4] = {av.x, av.y, av.z, av.w};
            float b[8] = {b0.x, b0.y, b0.z, b0.w, b1.x, b1.y, b1.z, b1.w};
#pragma unroll
            for (int i = 0; i < 4; i++)
#pragma unroll
                for (int j = 0; j < 8; j++)
                    acc[i][j] = fmaf(a[i], b[j], acc[i][j]);
        }
        __syncthreads();
    }

#pragma unroll
    for (int i = 0; i < 4; i++) {
        int r = m0 + tm * 4 + i;
#pragma unroll
        for (int j = 0; j < 8; j++) {
            int c = n0 + tn * 8 + j;
            if (NG && c >= N) continue;
            float v = acc[i][j];
            size_t o = (size_t)r * N + c;
            if (RESID) v += resid[o] + bias[c];
            C[o] = v;
        }
    }
}

// ---------------------------------------------------------------------------
// Causal depthwise conv1d (4 taps) over each directional sequence + SiLU.
// Gathers the permuted tokens directly from P (no materialized X).
// ---------------------------------------------------------------------------
__global__ __launch_bounds__(384)
void conv_kernel(const float* __restrict__ conv_w, const float* __restrict__ conv_b)
{
    const int t = blockIdx.x, n = blockIdx.y, d = threadIdx.x;
    const int dir = n >> 1, b = n & 1;
    float acc = conv_b[d];
#pragma unroll
    for (int k = 0; k < 4; k++) {
        int tt = t - 3 + k;
        if (tt >= 0) {
            int u = gmap(dir, tt);
            acc = fmaf(g_P[((size_t)(b * LSEQ + u)) * 768 + d], conv_w[d * 4 + k], acc);
        }
    }
    float s = acc / (1.f + __expf(-acc));        // silu
    g_xcs[((size_t)(n * LSEQ + t)) * DI + d] = s;
}

// ---------------------------------------------------------------------------
// dt = softplus(dt_lowrank @ dt_proj_w + b); store e1 = exp(-dt), dtx = dt*xc
// ---------------------------------------------------------------------------
__global__ __launch_bounds__(128)
void dt_kernel(const float* __restrict__ dt_proj_w, const float* __restrict__ dt_proj_b)
{
    const int row = blockIdx.x;
    __shared__ float lr[DTR];
    if (threadIdx.x < DTR) lr[threadIdx.x] = g_dbc[(size_t)row * 44 + threadIdx.x];
    __syncthreads();
#pragma unroll
    for (int j = 0; j < 3; j++) {
        int d = threadIdx.x + j * 128;
        float acc = dt_proj_b[d];
#pragma unroll
        for (int k = 0; k < DTR; k++) acc = fmaf(lr[k], dt_proj_w[k * DI + d], acc);
        float sp = fmaxf(acc, 0.f) + log1pf(__expf(-fabsf(acc)));   // softplus
        size_t idx = (size_t)row * DI + d;
        g_e1[idx]  = __expf(-sp);
        g_dtx[idx] = sp * g_xcs[idx];
    }
}

// Fast-path check: -A[d,s] == exp(A_log[d,s]) == s+1 (true for this problem).
__device__ __forceinline__ bool ladder_ok(const float* __restrict__ A_log, int d)
{
    bool ok = true;
#pragma unroll
    for (int s = 0; s < DS; s++) {
        float r = __expf(A_log[d * DS + s]);
        ok = ok && (fabsf(r - (float)(s + 1)) < 1e-3f);
    }
    return ok;
}

// ---------------------------------------------------------------------------
// S1: within-chunk recurrence with h0=0 -> chunk-local h_end + decay prod E
// ---------------------------------------------------------------------------
__global__ __launch_bounds__(384)
void scan1_kernel(const float* __restrict__ A_log)
{
    const int g = blockIdx.x, n = blockIdx.y, d = threadIdx.x;
    __shared__ float Bs[CH_T][DS];
    const int base = n * LSEQ + g * CH_T;
    for (int i = threadIdx.x; i < CH_T * DS; i += 384) {
        int t = i >> 4, s = i & 15;
        Bs[t][s] = g_dbc[(size_t)(base + t) * 44 + DTR + s];
    }
    __syncthreads();

    const bool fast = ladder_ok(A_log, d);
    float h[DS];
#pragma unroll
    for (int s = 0; s < DS; s++) h[s] = 0.f;
    float E = 1.f;

    if (fast) {
        for (int t = 0; t < CH_T; t++) {
            size_t idx = (size_t)(base + t) * DI + d;
            float e = g_e1[idx], u = g_dtx[idx];
            E *= e;
            float a = 1.f;
#pragma unroll
            for (int s = 0; s < DS; s++) {
                a *= e;                                  // a = e1^(s+1)
                h[s] = fmaf(h[s], a, u * Bs[t][s]);
            }
        }
    } else {
        for (int t = 0; t < CH_T; t++) {
            size_t idx = (size_t)(base + t) * DI + d;
            float e = g_e1[idx], u = g_dtx[idx];
            E *= e;
            float dtv = -__logf(e);
#pragma unroll
            for (int s = 0; s < DS; s++) {
                float a = __expf(-dtv * __expf(A_log[d * DS + s]));
                h[s] = fmaf(h[s], a, u * Bs[t][s]);
            }
        }
    }
    const int cg = n * CH_G + g;
#pragma unroll
    for (int s = 0; s < DS; s++)
        g_hend[((size_t)(cg * DS + s)) * DI + d] = h[s];
    g_E[(size_t)cg * DI + d] = E;
}

// ---------------------------------------------------------------------------
// S2: serial scan over 64 chunk summaries per channel -> per-chunk h0
// ---------------------------------------------------------------------------
__global__ __launch_bounds__(384)
void scan2_kernel(const float* __restrict__ A_log)
{
    const int s = blockIdx.x, n = blockIdx.y, d = threadIdx.x;
    float r = __expf(A_log[d * DS + s]);
    const bool fast = fabsf(r - (float)(s + 1)) < 1e-3f;
    float h = 0.f;
    for (int g = 0; g < CH_G; g++) {
        int cg = n * CH_G + g;
        float E = g_E[(size_t)cg * DI + d];
        float a;
        if (fast) {                       // E^(s+1) by binary powering
            a = 1.f; float p = E; int m = s + 1;
            while (m) { if (m & 1) a *= p; p *= p; m >>= 1; }
        } else {
            a = __powf(E, r);
        }
        size_t idx = ((size_t)(cg * DS + s)) * DI + d;
        g_h0[idx] = h;
        h = fmaf(a, h, g_hend[idx]);
    }
}

// ---------------------------------------------------------------------------
// S3: replay chunk from true h0, emit y = sum_s h*C + xc*D
// ---------------------------------------------------------------------------
__global__ __launch_bounds__(384)
void scan3_kernel(const float* __restrict__ A_log, const float* __restrict__ Dv)
{
    const int g = blockIdx.x, n = blockIdx.y, d = threadIdx.x;
    __shared__ float Bs[CH_T][DS], Cs[CH_T][DS];
    const int base = n * LSEQ + g * CH_T;
    for (int i = threadIdx.x; i < CH_T * DS; i += 384) {
        int t = i >> 4, s = i & 15;
        size_t ro = (size_t)(base + t) * 44;
        Bs[t][s] = g_dbc[ro + DTR + s];
        Cs[t][s] = g_dbc[ro + DTR + DS + s];
    }
    __syncthreads();

    const bool fast = ladder_ok(A_log, d);
    const int cg = n * CH_G + g;
    float h[DS];
#pragma unroll
    for (int s = 0; s < DS; s++)
        h[s] = g_h0[((size_t)(cg * DS + s)) * DI + d];
    const float Dd = Dv[d];

    if (fast) {
        for (int t = 0; t < CH_T; t++) {
            size_t idx = (size_t)(base + t) * DI + d;
            float e = g_e1[idx], u = g_dtx[idx];
            float a = 1.f, y = 0.f;
#pragma unroll
            for (int s = 0; s < DS; s++) {
                a *= e;
                h[s] = fmaf(h[s], a, u * Bs[t][s]);
                y = fmaf(h[s], Cs[t][s], y);
            }
            y = fmaf(g_xcs[idx], Dd, y);
            g_y[idx] = y;
        }
    } else {
        for (int t = 0; t < CH_T; t++) {
            size_t idx = (size_t)(base + t) * DI + d;
            float e = g_e1[idx], u = g_dtx[idx];
            float dtv = -__logf(e);
            float y = 0.f;
#pragma unroll
            for (int s = 0; s < DS; s++) {
                float a = __expf(-dtv * __expf(A_log[d * DS + s]));
                h[s] = fmaf(h[s], a, u * Bs[t][s]);
                y = fmaf(h[s], Cs[t][s], y);
            }
            y = fmaf(g_xcs[idx], Dd, y);
            g_y[idx] = y;
        }
    }
}

// ---------------------------------------------------------------------------
// Un-permute the 4 directional y's, sum, multiply by silu(z) (dir-invariant)
// ---------------------------------------------------------------------------
__global__ __launch_bounds__(384)
void gather_kernel()
{
    const int u = blockIdx.x, d = threadIdx.x;
    const int b = u >> 12, to = u & 4095;
    const int r = to >> 6, c = to & 63;
    const int t1 = (c << 6) + (63 - r);
    const int t2 = 4095 - to;
    const int t3 = ((63 - c) << 6) + r;
    float ys = g_y[((size_t)((0 + b) * LSEQ + to)) * DI + d]
             + g_y[((size_t)((2 + b) * LSEQ + t1)) * DI + d]
             + g_y[((size_t)((4 + b) * LSEQ + t2)) * DI + d]
             + g_y[((size_t)((6 + b) * LSEQ + t3)) * DI + d];
    float z  = g_P[((size_t)(b * LSEQ + to)) * 768 + DI + d];
    float sz = z / (1.f + __expf(-z));
    g_G[((size_t)u) * DI + d] = ys * sz;
}

// ---------------------------------------------------------------------------
// LayerNorm over 192 channels
// ---------------------------------------------------------------------------
__global__ __launch_bounds__(192)
void ln_kernel(const float* __restrict__ lg, const float* __restrict__ lb)
{
    const int u = blockIdx.x, j = threadIdx.x;
    float v = g_O1[(size_t)u * DM + j];
    __shared__ float rs[6], rq[6], stats[2];
    float s1 = v, s2 = v * v;
#pragma unroll
    for (int o = 16; o > 0; o >>= 1) {
        s1 += __shfl_down_sync(0xffffffffu, s1, o);
        s2 += __shfl_down_sync(0xffffffffu, s2, o);
    }
    if ((j & 31) == 0) { rs[j >> 5] = s1; rq[j >> 5] = s2; }
    __syncthreads();
    if (j == 0) {
        float a = 0.f, q = 0.f;
        for (int i = 0; i < 6; i++) { a += rs[i]; q += rq[i]; }
        float mu = a * (1.f / DM);
        float var = q * (1.f / DM) - mu * mu;
        stats[0] = mu; stats[1] = rsqrtf(var + 1e-5f);
    }
    __syncthreads();
    g_N1[(size_t)u * DM + j] = (v - stats[0]) * stats[1] * lg[j] + lb[j];
}

// ---------------------------------------------------------------------------
// Launch
// ---------------------------------------------------------------------------
extern "C" void kernel_launch(void* const* d_in, const int* in_sizes, int n_in,
                              void* d_out, int out_size)
{
    const float* x           = (const float*)d_in[0];
    const float* in_proj_w   = (const float*)d_in[1];
    const float* conv_w      = (const float*)d_in[2];
    const float* conv_b      = (const float*)d_in[3];
    const float* x_proj_w    = (const float*)d_in[4];
    const float* dt_proj_w   = (const float*)d_in[5];
    const float* dt_proj_b   = (const float*)d_in[6];
    const float* A_log       = (const float*)d_in[7];
    const float* Dv          = (const float*)d_in[8];
    const float* mamba_out_w = (const float*)d_in[9];
    const float* ln_g        = (const float*)d_in[10];
    const float* ln_b        = (const float*)d_in[11];
    const float* blk_w       = (const float*)d_in[12];
    const float* blk_b       = (const float*)d_in[13];
    float* out = (float*)d_out;

    float *P, *xcs, *dbc, *G, *O1, *N1;
    cudaGetSymbolAddress((void**)&P,   g_P);
    cudaGetSymbolAddress((void**)&xcs, g_xcs);
    cudaGetSymbolAddress((void**)&dbc, g_dbc);
    cudaGetSymbolAddress((void**)&G,   g_G);
    cudaGetSymbolAddress((void**)&O1,  g_O1);
    cudaGetSymbolAddress((void**)&N1,  g_N1);

    // 1) P = x @ in_proj_w              [8192,192]x[192,768]
    gemm64<false, false><<<dim3(12, 128), 128>>>(x, in_proj_w, P,
                                                 NTOK, 768, DM, nullptr, nullptr);
    // 2) depthwise conv + SiLU per direction (gathered)
    conv_kernel<<<dim3(LSEQ, NSEQ), 384>>>(conv_w, conv_b);
    // 3) dbc = xcs @ x_proj_w           [32768,384]x[384,44]
    gemm64<true, false><<<dim3(1, 512), 128>>>(xcs, x_proj_w, dbc,
                                               NROWS, 44, DI, nullptr, nullptr);
    // 4) dt / e1 / dtx
    dt_kernel<<<NROWS / 1, 128>>>(dt_proj_w, dt_proj_b);
    // 5-7) chunked selective scan
    scan1_kernel<<<dim3(CH_G, NSEQ), 384>>>(A_log);
    scan2_kernel<<<dim3(DS, NSEQ), 384>>>(A_log);
    scan3_kernel<<<dim3(CH_G, NSEQ), 384>>>(A_log, Dv);
    // 8) direction merge * silu(z)
    gather_kernel<<<NTOK, 384>>>();
    // 9) O1 = G @ mamba_out_w           [8192,384]x[384,192]
    gemm64<false, false><<<dim3(3, 128), 128>>>(G, mamba_out_w, O1,
                                                NTOK, DM, DI, nullptr, nullptr);
    // 10) LayerNorm
    ln_kernel<<<NTOK, DM>>>(ln_g, ln_b);
    // 11) out = x + N1 @ blk_w + blk_b
    gemm64<false, true><<<dim3(3, 128), 128>>>(N1, blk_w, out,
                                               NTOK, DM, DM, x, blk_b);
    (void)in_sizes; (void)n_in; (void)out_size;
}

// round 4
// speedup vs baseline: 1.1394x; 1.1394x over previous
#include <cuda_runtime.h>
#include <cstdint>

// ---------------------------------------------------------------------------
// Problem constants
// ---------------------------------------------------------------------------
#define LSEQ   4096
#define DM     192
#define DI     384
#define DS     16
#define DTR    12
#define NSEQ   8
#define NTOK   8192           // B * L
#define NROWS  32768          // NSEQ * L
#define CH_T   64             // chunk length
#define CH_G   64             // number of chunks

typedef unsigned long long ull;

// packed f32x2 helpers (sm_103a FFMA2 path)
__device__ __forceinline__ ull pk2(float lo, float hi) {
    ull r; asm("mov.b64 %0,{%1,%2};" : "=l"(r) : "f"(lo), "f"(hi)); return r;
}
__device__ __forceinline__ void upk(ull v, float& lo, float& hi) {
    asm("mov.b64 {%0,%1},%2;" : "=f"(lo), "=f"(hi) : "l"(v));
}
__device__ __forceinline__ ull fma2(ull a, ull b, ull c) {
    ull d; asm("fma.rn.f32x2 %0,%1,%2,%3;" : "=l"(d) : "l"(a), "l"(b), "l"(c)); return d;
}
__device__ __forceinline__ ull mul2(ull a, ull b) {
    ull d; asm("mul.rn.f32x2 %0,%1,%2;" : "=l"(d) : "l"(a), "l"(b)); return d;
}

// ---------------------------------------------------------------------------
// Scratch
// ---------------------------------------------------------------------------
__device__ float  g_P  [(size_t)NTOK  * 768];   // x @ in_proj_w
__device__ float  g_xcs[(size_t)NROWS * DI];    // silu(conv)
__device__ float  g_dbc[(size_t)NROWS * 44];    // xcs @ x_proj_w
__device__ float2 g_ed [(size_t)NROWS * DI];    // (exp(-dt), dt*xc)
__device__ float  g_hend[(size_t)NSEQ * CH_G * DS * DI];
__device__ float  g_h0  [(size_t)NSEQ * CH_G * DS * DI];
__device__ float  g_E  [(size_t)NSEQ * CH_G * DI];
__device__ float  g_y  [(size_t)NROWS * DI];
__device__ float  g_G  [(size_t)NTOK  * DI];
__device__ float  g_O1 [(size_t)NTOK  * DM];
__device__ float  g_N1 [(size_t)NTOK  * DM];

__device__ __forceinline__ int gmap(int dir, int t) {
    int p = t >> 6, q = t & 63;
    switch (dir) {
        case 0:  return t;
        case 1:  return ((63 - q) << 6) + p;
        case 2:  return ((63 - p) << 6) + (63 - q);
        default: return (q << 6) + (63 - p);
    }
}

// ---------------------------------------------------------------------------
// FP32 GEMM with packed f32x2 FMA: C[M,N] = A[M,K] @ W[K,N] (+resid+bias)
// Tile 128x64, BK=16, 128 threads, 8x8 microtile, register-prefetch pipeline.
// Requires M%128==0, K%16==0, N%4==0 (N guarded by NG).
// ---------------------------------------------------------------------------
template<bool NG, bool RESID>
__global__ __launch_bounds__(128, 4)
void gemm_f2(const float* __restrict__ A, const float* __restrict__ W,
             float* __restrict__ C, int M, int N, int K,
             const float* __restrict__ resid, const float* __restrict__ bias)
{
    __shared__ __align__(16) float As[16][132];   // padded rows (STS 2-way max)
    __shared__ __align__(16) float Bs[16][64];

    const int tid = threadIdx.x;
    const int tm = tid >> 3, tn = tid & 7;
    const int m0 = blockIdx.y * 128, n0 = blockIdx.x * 64;

    float4 rA[4], rB[2];

    auto loadA = [&](int k0) {
#pragma unroll
        for (int e = 0; e < 4; e++) {
            int l = e * 128 + tid; int r = l >> 2, kv = l & 3;
            rA[e] = *reinterpret_cast<const float4*>(&A[(size_t)(m0 + r) * K + k0 + kv * 4]);
        }
    };
    auto loadB = [&](int k0) {
#pragma unroll
        for (int e = 0; e < 2; e++) {
            int l = e * 128 + tid; int kk = l >> 4, c4 = l & 15;
            float4 w = make_float4(0.f, 0.f, 0.f, 0.f);
            if (!NG || (n0 + c4 * 4) < N)
                w = *reinterpret_cast<const float4*>(&W[(size_t)(k0 + kk) * N + n0 + c4 * 4]);
            rB[e] = w;
        }
    };
    auto stA = [&]() {
#pragma unroll
        for (int e = 0; e < 4; e++) {
            int l = e * 128 + tid; int r = l >> 2, kv = l & 3;
            As[kv * 4 + 0][r] = rA[e].x; As[kv * 4 + 1][r] = rA[e].y;
            As[kv * 4 + 2][r] = rA[e].z; As[kv * 4 + 3][r] = rA[e].w;
        }
    };
    auto stB = [&]() {
#pragma unroll
        for (int e = 0; e < 2; e++) {
            int l = e * 128 + tid; int kk = l >> 4, c4 = l & 15;
            *reinterpret_cast<float4*>(&Bs[kk][c4 * 4]) = rB[e];
        }
    };

    ull acc[8][4];
#pragma unroll
    for (int i = 0; i < 8; i++)
#pragma unroll
        for (int j = 0; j < 4; j++) acc[i][j] = 0ull;

    loadA(0); loadB(0);
    const int KT = K / 16;
    for (int kt = 0; kt < KT; kt++) {
        stA(); stB();
        __syncthreads();
        if (kt + 1 < KT) { loadA((kt + 1) * 16); loadB((kt + 1) * 16); }
#pragma unroll
        for (int kk = 0; kk < 16; kk++) {
            float4 a0 = *reinterpret_cast<const float4*>(&As[kk][tm * 8]);
            float4 a1 = *reinterpret_cast<const float4*>(&As[kk][tm * 8 + 4]);
            ull b[4];
#pragma unroll
            for (int j = 0; j < 4; j++)
                b[j] = *reinterpret_cast<const ull*>(&Bs[kk][tn * 8 + 2 * j]);
            float av[8] = {a0.x, a0.y, a0.z, a0.w, a1.x, a1.y, a1.z, a1.w};
#pragma unroll
            for (int i = 0; i < 8; i++) {
                ull ap = pk2(av[i], av[i]);
#pragma unroll
                for (int j = 0; j < 4; j++)
                    acc[i][j] = fma2(ap, b[j], acc[i][j]);
            }
        }
        __syncthreads();
    }

#pragma unroll
    for (int i = 0; i < 8; i++) {
        int r = m0 + tm * 8 + i;
#pragma unroll
        for (int j = 0; j < 4; j++) {
            int c = n0 + tn * 8 + 2 * j;
            if (NG && c >= N) continue;
            float lo, hi; upk(acc[i][j], lo, hi);
            size_t o = (size_t)r * N + c;
            if (RESID) { lo += resid[o] + bias[c]; hi += resid[o + 1] + bias[c + 1]; }
            float2 v = make_float2(lo, hi);
            *reinterpret_cast<float2*>(&C[o]) = v;
        }
    }
}

// ---------------------------------------------------------------------------
// Causal depthwise conv1d (4 taps) + SiLU, gathered from P.
// ---------------------------------------------------------------------------
__global__ __launch_bounds__(384)
void conv_kernel(const float* __restrict__ conv_w, const float* __restrict__ conv_b)
{
    const int t = blockIdx.x, n = blockIdx.y, d = threadIdx.x;
    const int dir = n >> 1, b = n & 1;
    float acc = conv_b[d];
#pragma unroll
    for (int k = 0; k < 4; k++) {
        int tt = t - 3 + k;
        if (tt >= 0) {
            int u = gmap(dir, tt);
            acc = fmaf(g_P[((size_t)(b * LSEQ + u)) * 768 + d], conv_w[d * 4 + k], acc);
        }
    }
    float s = acc / (1.f + __expf(-acc));
    g_xcs[((size_t)(n * LSEQ + t)) * DI + d] = s;
}

// ---------------------------------------------------------------------------
// dt: 32 rows/block; dt_proj_w staged in smem once (kills L2 re-read).
// Writes packed (e1, dt*xc).
// ---------------------------------------------------------------------------
__global__ __launch_bounds__(384)
void dt_kernel(const float* __restrict__ dt_proj_w, const float* __restrict__ dt_proj_b)
{
    __shared__ float Ws[DTR][DI];
    __shared__ float lr[32][DTR];
    const int tid = threadIdx.x;
    const int row0 = blockIdx.x * 32;

    for (int i = tid; i < DTR * DI; i += 384)
        Ws[i / DI][i % DI] = dt_proj_w[i];
    {
        int r = tid / DTR, k = tid % DTR;          // 384 = 32*12
        lr[r][k] = g_dbc[(size_t)(row0 + r) * 44 + k];
    }
    __syncthreads();

    const int d = tid;
    const float bias = dt_proj_b[d];
    for (int r = 0; r < 32; r++) {
        float a = bias;
#pragma unroll
        for (int k = 0; k < DTR; k++) a = fmaf(lr[r][k], Ws[k][d], a);
        float sp = fmaxf(a, 0.f) + log1pf(__expf(-fabsf(a)));
        size_t idx = (size_t)(row0 + r) * DI + d;
        float xc = g_xcs[idx];
        g_ed[idx] = make_float2(__expf(-sp), sp * xc);
    }
}

// Fast-path check: -A[d,s] == exp(A_log[d,s]) == s+1 for this problem.
__device__ __forceinline__ bool ladder_ok(const float* __restrict__ A_log, int d)
{
    bool ok = true;
#pragma unroll
    for (int s = 0; s < DS; s++) {
        float r = __expf(A_log[d * DS + s]);
        ok = ok && (fabsf(r - (float)(s + 1)) < 1e-3f);
    }
    return ok;
}

// ---------------------------------------------------------------------------
// S1: within-chunk recurrence (h0=0) -> h_end + decay product E
// ---------------------------------------------------------------------------
__global__ __launch_bounds__(384)
void scan1_kernel(const float* __restrict__ A_log)
{
    const int g = blockIdx.x, n = blockIdx.y, d = threadIdx.x;
    __shared__ __align__(16) float Bs[CH_T][DS];
    const int base = n * LSEQ + g * CH_T;
    for (int i = threadIdx.x; i < CH_T * DS; i += 384) {
        int t = i >> 4, s = i & 15;
        Bs[t][s] = g_dbc[(size_t)(base + t) * 44 + DTR + s];
    }
    __syncthreads();

    const bool fast = ladder_ok(A_log, d);
    float E = 1.f;
    const int cg = n * CH_G + g;

    if (fast) {
        ull h[8];
#pragma unroll
        for (int j = 0; j < 8; j++) h[j] = 0ull;
        for (int t = 0; t < CH_T; t++) {
            float2 eu = g_ed[(size_t)(base + t) * DI + d];
            float e = eu.x, u = eu.y;
            E *= e;
            float e2 = e * e;
            ull e2p = pk2(e2, e2);
            ull up  = pk2(u, u);
            ull ap  = pk2(e, e2);
#pragma unroll
            for (int j = 0; j < 8; j++) {
                ull Bp = *reinterpret_cast<const ull*>(&Bs[t][2 * j]);
                h[j] = fma2(h[j], ap, mul2(up, Bp));
                if (j < 7) ap = mul2(ap, e2p);
            }
        }
#pragma unroll
        for (int j = 0; j < 8; j++) {
            float lo, hi; upk(h[j], lo, hi);
            g_hend[((size_t)(cg * DS + 2 * j))     * DI + d] = lo;
            g_hend[((size_t)(cg * DS + 2 * j + 1)) * DI + d] = hi;
        }
    } else {
        float h[DS];
#pragma unroll
        for (int s = 0; s < DS; s++) h[s] = 0.f;
        for (int t = 0; t < CH_T; t++) {
            float2 eu = g_ed[(size_t)(base + t) * DI + d];
            float e = eu.x, u = eu.y;
            E *= e;
            float dtv = -__logf(e);
#pragma unroll
            for (int s = 0; s < DS; s++) {
                float a = __expf(-dtv * __expf(A_log[d * DS + s]));
                h[s] = fmaf(h[s], a, u * Bs[t][s]);
            }
        }
#pragma unroll
        for (int s = 0; s < DS; s++)
            g_hend[((size_t)(cg * DS + s)) * DI + d] = h[s];
    }
    g_E[(size_t)cg * DI + d] = E;
}

// ---------------------------------------------------------------------------
// S2: serial scan over 64 chunk summaries per channel -> per-chunk h0
// ---------------------------------------------------------------------------
__global__ __launch_bounds__(384)
void scan2_kernel(const float* __restrict__ A_log)
{
    const int s = blockIdx.x, n = blockIdx.y, d = threadIdx.x;
    float r = __expf(A_log[d * DS + s]);
    const bool fast = fabsf(r - (float)(s + 1)) < 1e-3f;
    float h = 0.f;
    for (int g = 0; g < CH_G; g++) {
        int cg = n * CH_G + g;
        float E = g_E[(size_t)cg * DI + d];
        float a;
        if (fast) {
            a = 1.f; float p = E; int m = s + 1;
            while (m) { if (m & 1) a *= p; p *= p; m >>= 1; }
        } else {
            a = __powf(E, r);
        }
        size_t idx = ((size_t)(cg * DS + s)) * DI + d;
        g_h0[idx] = h;
        h = fmaf(a, h, g_hend[idx]);
    }
}

// ---------------------------------------------------------------------------
// S3: replay chunk from true h0, emit y
// ---------------------------------------------------------------------------
__global__ __launch_bounds__(384)
void scan3_kernel(const float* __restrict__ A_log, const float* __restrict__ Dv)
{
    const int g = blockIdx.x, n = blockIdx.y, d = threadIdx.x;
    __shared__ __align__(16) float Bs[CH_T][DS];
    __shared__ __align__(16) float Cs[CH_T][DS];
    const int base = n * LSEQ + g * CH_T;
    for (int i = threadIdx.x; i < CH_T * DS; i += 384) {
        int t = i >> 4, s = i & 15;
        size_t ro = (size_t)(base + t) * 44;
        Bs[t][s] = g_dbc[ro + DTR + s];
        Cs[t][s] = g_dbc[ro + DTR + DS + s];
    }
    __syncthreads();

    const bool fast = ladder_ok(A_log, d);
    const int cg = n * CH_G + g;
    const float Dd = Dv[d];

    if (fast) {
        ull h[8];
#pragma unroll
        for (int j = 0; j < 8; j++)
            h[j] = pk2(g_h0[((size_t)(cg * DS + 2 * j))     * DI + d],
                       g_h0[((size_t)(cg * DS + 2 * j + 1)) * DI + d]);
        for (int t = 0; t < CH_T; t++) {
            size_t idx = (size_t)(base + t) * DI + d;
            float2 eu = g_ed[idx];
            float e = eu.x, u = eu.y;
            float e2 = e * e;
            ull e2p = pk2(e2, e2);
            ull up  = pk2(u, u);
            ull ap  = pk2(e, e2);
            ull y2  = 0ull;
#pragma unroll
            for (int j = 0; j < 8; j++) {
                ull Bp = *reinterpret_cast<const ull*>(&Bs[t][2 * j]);
                ull Cp = *reinterpret_cast<const ull*>(&Cs[t][2 * j]);
                h[j] = fma2(h[j], ap, mul2(up, Bp));
                y2   = fma2(h[j], Cp, y2);
                if (j < 7) ap = mul2(ap, e2p);
            }
            float ylo, yhi; upk(y2, ylo, yhi);
            float y = ylo + yhi;
            y = fmaf(g_xcs[idx], Dd, y);
            g_y[idx] = y;
        }
    } else {
        float h[DS];
#pragma unroll
        for (int s = 0; s < DS; s++)
            h[s] = g_h0[((size_t)(cg * DS + s)) * DI + d];
        for (int t = 0; t < CH_T; t++) {
            size_t idx = (size_t)(base + t) * DI + d;
            float2 eu = g_ed[idx];
            float e = eu.x, u = eu.y;
            float dtv = -__logf(e);
            float y = 0.f;
#pragma unroll
            for (int s = 0; s < DS; s++) {
                float a = __expf(-dtv * __expf(A_log[d * DS + s]));
                h[s] = fmaf(h[s], a, u * Bs[t][s]);
                y = fmaf(h[s], Cs[t][s], y);
            }
            y = fmaf(g_xcs[idx], Dd, y);
            g_y[idx] = y;
        }
    }
}

// ---------------------------------------------------------------------------
// Un-permute 4 directions, sum, multiply by silu(z)
// ---------------------------------------------------------------------------
__global__ __launch_bounds__(384)
void gather_kernel()
{
    const int u = blockIdx.x, d = threadIdx.x;
    const int b = u >> 12, to = u & 4095;
    const int r = to >> 6, c = to & 63;
    const int t1 = (c << 6) + (63 - r);
    const int t2 = 4095 - to;
    const int t3 = ((63 - c) << 6) + r;
    float ys = g_y[((size_t)((0 + b) * LSEQ + to)) * DI + d]
             + g_y[((size_t)((2 + b) * LSEQ + t1)) * DI + d]
             + g_y[((size_t)((4 + b) * LSEQ + t2)) * DI + d]
             + g_y[((size_t)((6 + b) * LSEQ + t3)) * DI + d];
    float z  = g_P[((size_t)(b * LSEQ + to)) * 768 + DI + d];
    float sz = z / (1.f + __expf(-z));
    g_G[((size_t)u) * DI + d] = ys * sz;
}

// ---------------------------------------------------------------------------
// LayerNorm over 192 channels
// ---------------------------------------------------------------------------
__global__ __launch_bounds__(192)
void ln_kernel(const float* __restrict__ lg, const float* __restrict__ lb)
{
    const int u = blockIdx.x, j = threadIdx.x;
    float v = g_O1[(size_t)u * DM + j];
    __shared__ float rs[6], rq[6], stats[2];
    float s1 = v, s2 = v * v;
#pragma unroll
    for (int o = 16; o > 0; o >>= 1) {
        s1 += __shfl_down_sync(0xffffffffu, s1, o);
        s2 += __shfl_down_sync(0xffffffffu, s2, o);
    }
    if ((j & 31) == 0) { rs[j >> 5] = s1; rq[j >> 5] = s2; }
    __syncthreads();
    if (j == 0) {
        float a = 0.f, q = 0.f;
        for (int i = 0; i < 6; i++) { a += rs[i]; q += rq[i]; }
        float mu = a * (1.f / DM);
        float var = q * (1.f / DM) - mu * mu;
        stats[0] = mu; stats[1] = rsqrtf(var + 1e-5f);
    }
    __syncthreads();
    g_N1[(size_t)u * DM + j] = (v - stats[0]) * stats[1] * lg[j] + lb[j];
}

// ---------------------------------------------------------------------------
// Launch
// ---------------------------------------------------------------------------
extern "C" void kernel_launch(void* const* d_in, const int* in_sizes, int n_in,
                              void* d_out, int out_size)
{
    const float* x           = (const float*)d_in[0];
    const float* in_proj_w   = (const float*)d_in[1];
    const float* conv_w      = (const float*)d_in[2];
    const float* conv_b      = (const float*)d_in[3];
    const float* x_proj_w    = (const float*)d_in[4];
    const float* dt_proj_w   = (const float*)d_in[5];
    const float* dt_proj_b   = (const float*)d_in[6];
    const float* A_log       = (const float*)d_in[7];
    const float* Dv          = (const float*)d_in[8];
    const float* mamba_out_w = (const float*)d_in[9];
    const float* ln_g        = (const float*)d_in[10];
    const float* ln_b        = (const float*)d_in[11];
    const float* blk_w       = (const float*)d_in[12];
    const float* blk_b       = (const float*)d_in[13];
    float* out = (float*)d_out;

    float *P, *xcs, *dbc, *G, *O1, *N1;
    cudaGetSymbolAddress((void**)&P,   g_P);
    cudaGetSymbolAddress((void**)&xcs, g_xcs);
    cudaGetSymbolAddress((void**)&dbc, g_dbc);
    cudaGetSymbolAddress((void**)&G,   g_G);
    cudaGetSymbolAddress((void**)&O1,  g_O1);
    cudaGetSymbolAddress((void**)&N1,  g_N1);

    // 1) P = x @ in_proj_w              [8192,192]x[192,768]
    gemm_f2<false, false><<<dim3(12, 64), 128>>>(x, in_proj_w, P,
                                                 NTOK, 768, DM, nullptr, nullptr);
    // 2) depthwise conv + SiLU per direction
    conv_kernel<<<dim3(LSEQ, NSEQ), 384>>>(conv_w, conv_b);
    // 3) dbc = xcs @ x_proj_w           [32768,384]x[384,44]
    gemm_f2<true, false><<<dim3(1, 256), 128>>>(xcs, x_proj_w, dbc,
                                                NROWS, 44, DI, nullptr, nullptr);
    // 4) dt -> packed (e1, dt*xc)
    dt_kernel<<<NROWS / 32, 384>>>(dt_proj_w, dt_proj_b);
    // 5-7) chunked selective scan
    scan1_kernel<<<dim3(CH_G, NSEQ), 384>>>(A_log);
    scan2_kernel<<<dim3(DS, NSEQ), 384>>>(A_log);
    scan3_kernel<<<dim3(CH_G, NSEQ), 384>>>(A_log, Dv);
    // 8) direction merge * silu(z)
    gather_kernel<<<NTOK, 384>>>();
    // 9) O1 = G @ mamba_out_w           [8192,384]x[384,192]
    gemm_f2<false, false><<<dim3(3, 64), 128>>>(G, mamba_out_w, O1,
                                                NTOK, DM, DI, nullptr, nullptr);
    // 10) LayerNorm
    ln_kernel<<<NTOK, DM>>>(ln_g, ln_b);
    // 11) out = x + N1 @ blk_w + blk_b
    gemm_f2<false, true><<<dim3(3, 64), 128>>>(N1, blk_w, out,
                                               NTOK, DM, DM, x, blk_b);
    (void)in_sizes; (void)n_in; (void)out_size;
}

// round 5
// speedup vs baseline: 1.2708x; 1.1154x over previous
#include <cuda_runtime.h>
#include <cstdint>

// ---------------------------------------------------------------------------
// Problem constants
// ---------------------------------------------------------------------------
#define LSEQ   4096
#define DM     192
#define DI     384
#define DS     16
#define DTR    12
#define NSEQ   8
#define NTOK   8192           // B * L
#define NROWS  32768          // NSEQ * L
#define CH_T   64             // chunk length
#define CH_G   64             // number of chunks

typedef unsigned long long ull;

// packed f32x2 helpers (sm_103a FFMA2 path)
__device__ __forceinline__ ull pk2(float lo, float hi) {
    ull r; asm("mov.b64 %0,{%1,%2};" : "=l"(r) : "f"(lo), "f"(hi)); return r;
}
__device__ __forceinline__ void upk(ull v, float& lo, float& hi) {
    asm("mov.b64 {%0,%1},%2;" : "=f"(lo), "=f"(hi) : "l"(v));
}
__device__ __forceinline__ ull fma2(ull a, ull b, ull c) {
    ull d; asm("fma.rn.f32x2 %0,%1,%2,%3;" : "=l"(d) : "l"(a), "l"(b), "l"(c)); return d;
}
__device__ __forceinline__ ull mul2(ull a, ull b) {
    ull d; asm("mul.rn.f32x2 %0,%1,%2;" : "=l"(d) : "l"(a), "l"(b)); return d;
}

// ---------------------------------------------------------------------------
// Scratch
// ---------------------------------------------------------------------------
__device__ float  g_P  [(size_t)NTOK  * 768];   // x @ in_proj_w
__device__ float  g_xcs[(size_t)NROWS * DI];    // silu(conv)
__device__ float  g_dbc[(size_t)NROWS * 44];    // xcs @ x_proj_w
__device__ float  g_hend[(size_t)NSEQ * CH_G * DS * DI];
__device__ float  g_h0  [(size_t)NSEQ * CH_G * DS * DI];
__device__ float  g_E  [(size_t)NSEQ * CH_G * DI];
__device__ float  g_y  [(size_t)NROWS * DI];    // y, stored UN-permuted: [n][orig_token][d]
__device__ float  g_G  [(size_t)NTOK  * DI];
__device__ float  g_O1 [(size_t)NTOK  * DM];
__device__ float  g_N1 [(size_t)NTOK  * DM];

__device__ __forceinline__ int gmap(int dir, int t) {
    int p = t >> 6, q = t & 63;
    switch (dir) {
        case 0:  return t;
        case 1:  return ((63 - q) << 6) + p;
        case 2:  return ((63 - p) << 6) + (63 - q);
        default: return (q << 6) + (63 - p);
    }
}

// ---------------------------------------------------------------------------
// FP32 GEMM with packed f32x2 FMA: C[M,N] = A[M,K] @ W[K,N] (+resid+bias)
// Tile 128x64, BK=16, 128 threads, 8x8 microtile, register-prefetch pipeline.
// ---------------------------------------------------------------------------
template<bool NG, bool RESID>
__global__ __launch_bounds__(128, 4)
void gemm_f2(const float* __restrict__ A, const float* __restrict__ W,
             float* __restrict__ C, int M, int N, int K,
             const float* __restrict__ resid, const float* __restrict__ bias)
{
    __shared__ __align__(16) float As[16][132];
    __shared__ __align__(16) float Bs[16][64];

    const int tid = threadIdx.x;
    const int tm = tid >> 3, tn = tid & 7;
    const int m0 = blockIdx.y * 128, n0 = blockIdx.x * 64;

    float4 rA[4], rB[2];

    auto loadA = [&](int k0) {
#pragma unroll
        for (int e = 0; e < 4; e++) {
            int l = e * 128 + tid; int r = l >> 2, kv = l & 3;
            rA[e] = *reinterpret_cast<const float4*>(&A[(size_t)(m0 + r) * K + k0 + kv * 4]);
        }
    };
    auto loadB = [&](int k0) {
#pragma unroll
        for (int e = 0; e < 2; e++) {
            int l = e * 128 + tid; int kk = l >> 4, c4 = l & 15;
            float4 w = make_float4(0.f, 0.f, 0.f, 0.f);
            if (!NG || (n0 + c4 * 4) < N)
                w = *reinterpret_cast<const float4*>(&W[(size_t)(k0 + kk) * N + n0 + c4 * 4]);
            rB[e] = w;
        }
    };
    auto stA = [&]() {
#pragma unroll
        for (int e = 0; e < 4; e++) {
            int l = e * 128 + tid; int r = l >> 2, kv = l & 3;
            As[kv * 4 + 0][r] = rA[e].x; As[kv * 4 + 1][r] = rA[e].y;
            As[kv * 4 + 2][r] = rA[e].z; As[kv * 4 + 3][r] = rA[e].w;
        }
    };
    auto stB = [&]() {
#pragma unroll
        for (int e = 0; e < 2; e++) {
            int l = e * 128 + tid; int kk = l >> 4, c4 = l & 15;
            *reinterpret_cast<float4*>(&Bs[kk][c4 * 4]) = rB[e];
        }
    };

    ull acc[8][4];
#pragma unroll
    for (int i = 0; i < 8; i++)
#pragma unroll
        for (int j = 0; j < 4; j++) acc[i][j] = 0ull;

    loadA(0); loadB(0);
    const int KT = K / 16;
    for (int kt = 0; kt < KT; kt++) {
        stA(); stB();
        __syncthreads();
        if (kt + 1 < KT) { loadA((kt + 1) * 16); loadB((kt + 1) * 16); }
#pragma unroll
        for (int kk = 0; kk < 16; kk++) {
            float4 a0 = *reinterpret_cast<const float4*>(&As[kk][tm * 8]);
            float4 a1 = *reinterpret_cast<const float4*>(&As[kk][tm * 8 + 4]);
            ull b[4];
#pragma unroll
            for (int j = 0; j < 4; j++)
                b[j] = *reinterpret_cast<const ull*>(&Bs[kk][tn * 8 + 2 * j]);
            float av[8] = {a0.x, a0.y, a0.z, a0.w, a1.x, a1.y, a1.z, a1.w};
#pragma unroll
            for (int i = 0; i < 8; i++) {
                ull ap = pk2(av[i], av[i]);
#pragma unroll
                for (int j = 0; j < 4; j++)
                    acc[i][j] = fma2(ap, b[j], acc[i][j]);
            }
        }
        __syncthreads();
    }

#pragma unroll
    for (int i = 0; i < 8; i++) {
        int r = m0 + tm * 8 + i;
#pragma unroll
        for (int j = 0; j < 4; j++) {
            int c = n0 + tn * 8 + 2 * j;
            if (NG && c >= N) continue;
            float lo, hi; upk(acc[i][j], lo, hi);
            size_t o = (size_t)r * N + c;
            if (RESID) { lo += resid[o] + bias[c]; hi += resid[o + 1] + bias[c + 1]; }
            float2 v = make_float2(lo, hi);
            *reinterpret_cast<float2*>(&C[o]) = v;
        }
    }
}

// ---------------------------------------------------------------------------
// Causal depthwise conv1d (4 taps) + SiLU, gathered from P.
// ---------------------------------------------------------------------------
__global__ __launch_bounds__(384)
void conv_kernel(const float* __restrict__ conv_w, const float* __restrict__ conv_b)
{
    const int t = blockIdx.x, n = blockIdx.y, d = threadIdx.x;
    const int dir = n >> 1, b = n & 1;
    float acc = conv_b[d];
#pragma unroll
    for (int k = 0; k < 4; k++) {
        int tt = t - 3 + k;
        if (tt >= 0) {
            int u = gmap(dir, tt);
            acc = fmaf(g_P[((size_t)(b * LSEQ + u)) * 768 + d], conv_w[d * 4 + k], acc);
        }
    }
    float s = acc / (1.f + __expf(-acc));
    g_xcs[((size_t)(n * LSEQ + t)) * DI + d] = s;
}

// Fast-path check: -A[d,s] == exp(A_log[d,s]) == s+1 for this problem.
__device__ __forceinline__ bool ladder_ok(const float* __restrict__ A_log, int d)
{
    bool ok = true;
#pragma unroll
    for (int s = 0; s < DS; s++) {
        float r = __expf(A_log[d * DS + s]);
        ok = ok && (fabsf(r - (float)(s + 1)) < 1e-3f);
    }
    return ok;
}

// Fused dt: a = bias + lr·Wc  ->  e1 = 1/(1+e^a)  (= exp(-softplus(a)))
//                                  dt = log(1+e^a) (= softplus(a))
__device__ __forceinline__ void dt_eval(const float* __restrict__ lr_t,
                                        const float* __restrict__ Wc, float bias,
                                        float& e1, float& dt)
{
    float a = bias;
#pragma unroll
    for (int k = 0; k < DTR; k++) a = fmaf(lr_t[k], Wc[k], a);
    float ea = __expf(a);
    float op = 1.f + ea;
    e1 = __fdividef(1.f, op);
    dt = __logf(op);
}

// ---------------------------------------------------------------------------
// S1: within-chunk recurrence (h0=0) -> h_end + decay product E.
// dt computed inline from low-rank dbc (no g_ed pass).
// ---------------------------------------------------------------------------
__global__ __launch_bounds__(384)
void scan1_kernel(const float* __restrict__ A_log,
                  const float* __restrict__ dt_proj_w, const float* __restrict__ dt_proj_b)
{
    const int g = blockIdx.x, n = blockIdx.y, d = threadIdx.x;
    __shared__ __align__(16) float Bs[CH_T][DS];
    __shared__ float lr[CH_T][DTR];
    const int base = n * LSEQ + g * CH_T;
    for (int i = threadIdx.x; i < CH_T * DS; i += 384) {
        int t = i >> 4, s = i & 15;
        Bs[t][s] = g_dbc[(size_t)(base + t) * 44 + DTR + s];
    }
    for (int i = threadIdx.x; i < CH_T * DTR; i += 384)
        lr[i / DTR][i % DTR] = g_dbc[(size_t)(base + i / DTR) * 44 + (i % DTR)];

    float Wc[DTR];
#pragma unroll
    for (int k = 0; k < DTR; k++) Wc[k] = dt_proj_w[k * DI + d];
    const float bias = dt_proj_b[d];
    __syncthreads();

    const bool fast = ladder_ok(A_log, d);
    float E = 1.f;
    const int cg = n * CH_G + g;

    if (fast) {
        ull h[8];
#pragma unroll
        for (int j = 0; j < 8; j++) h[j] = 0ull;
        for (int t = 0; t < CH_T; t++) {
            float e, dt;
            dt_eval(lr[t], Wc, bias, e, dt);
            float u = dt * g_xcs[(size_t)(base + t) * DI + d];
            E *= e;
            float e2 = e * e;
            ull e2p = pk2(e2, e2);
            ull up  = pk2(u, u);
            ull ap  = pk2(e, e2);
#pragma unroll
            for (int j = 0; j < 8; j++) {
                ull Bp = *reinterpret_cast<const ull*>(&Bs[t][2 * j]);
                h[j] = fma2(h[j], ap, mul2(up, Bp));
                if (j < 7) ap = mul2(ap, e2p);
            }
        }
#pragma unroll
        for (int j = 0; j < 8; j++) {
            float lo, hi; upk(h[j], lo, hi);
            g_hend[((size_t)(cg * DS + 2 * j))     * DI + d] = lo;
            g_hend[((size_t)(cg * DS + 2 * j + 1)) * DI + d] = hi;
        }
    } else {
        float h[DS];
#pragma unroll
        for (int s = 0; s < DS; s++) h[s] = 0.f;
        for (int t = 0; t < CH_T; t++) {
            float e, dtv;
            dt_eval(lr[t], Wc, bias, e, dtv);
            float u = dtv * g_xcs[(size_t)(base + t) * DI + d];
            E *= e;
#pragma unroll
            for (int s = 0; s < DS; s++) {
                float a = __expf(-dtv * __expf(A_log[d * DS + s]));
                h[s] = fmaf(h[s], a, u * Bs[t][s]);
            }
        }
#pragma unroll
        for (int s = 0; s < DS; s++)
            g_hend[((size_t)(cg * DS + s)) * DI + d] = h[s];
    }
    g_E[(size_t)cg * DI + d] = E;
}

// ---------------------------------------------------------------------------
// S2: serial scan over 64 chunk summaries per channel -> per-chunk h0
// ---------------------------------------------------------------------------
__global__ __launch_bounds__(384)
void scan2_kernel(const float* __restrict__ A_log)
{
    const int s = blockIdx.x, n = blockIdx.y, d = threadIdx.x;
    float r = __expf(A_log[d * DS + s]);
    const bool fast = fabsf(r - (float)(s + 1)) < 1e-3f;
    float h = 0.f;
    for (int g = 0; g < CH_G; g++) {
        int cg = n * CH_G + g;
        float E = g_E[(size_t)cg * DI + d];
        float a;
        if (fast) {
            a = 1.f; float p = E; int m = s + 1;
            while (m) { if (m & 1) a *= p; p *= p; m >>= 1; }
        } else {
            a = __powf(E, r);
        }
        size_t idx = ((size_t)(cg * DS + s)) * DI + d;
        g_h0[idx] = h;
        h = fmaf(a, h, g_hend[idx]);
    }
}

// ---------------------------------------------------------------------------
// S3: replay chunk from true h0, emit y (written UN-permuted by gmap).
// dt computed inline (no g_ed).
// ---------------------------------------------------------------------------
__global__ __launch_bounds__(384)
void scan3_kernel(const float* __restrict__ A_log, const float* __restrict__ Dv,
                  const float* __restrict__ dt_proj_w, const float* __restrict__ dt_proj_b)
{
    const int g = blockIdx.x, n = blockIdx.y, d = threadIdx.x;
    const int dir = n >> 1;
    __shared__ __align__(16) float Bs[CH_T][DS];
    __shared__ __align__(16) float Cs[CH_T][DS];
    __shared__ float lr[CH_T][DTR];
    const int base = n * LSEQ + g * CH_T;
    for (int i = threadIdx.x; i < CH_T * DS; i += 384) {
        int t = i >> 4, s = i & 15;
        size_t ro = (size_t)(base + t) * 44;
        Bs[t][s] = g_dbc[ro + DTR + s];
        Cs[t][s] = g_dbc[ro + DTR + DS + s];
    }
    for (int i = threadIdx.x; i < CH_T * DTR; i += 384)
        lr[i / DTR][i % DTR] = g_dbc[(size_t)(base + i / DTR) * 44 + (i % DTR)];

    float Wc[DTR];
#pragma unroll
    for (int k = 0; k < DTR; k++) Wc[k] = dt_proj_w[k * DI + d];
    const float bias = dt_proj_b[d];
    __syncthreads();

    const bool fast = ladder_ok(A_log, d);
    const int cg = n * CH_G + g;
    const float Dd = Dv[d];

    if (fast) {
        ull h[8];
#pragma unroll
        for (int j = 0; j < 8; j++)
            h[j] = pk2(g_h0[((size_t)(cg * DS + 2 * j))     * DI + d],
                       g_h0[((size_t)(cg * DS + 2 * j + 1)) * DI + d]);
        for (int t = 0; t < CH_T; t++) {
            size_t idx = (size_t)(base + t) * DI + d;
            float e, dt;
            dt_eval(lr[t], Wc, bias, e, dt);
            float xc = g_xcs[idx];
            float u = dt * xc;
            float e2 = e * e;
            ull e2p = pk2(e2, e2);
            ull up  = pk2(u, u);
            ull ap  = pk2(e, e2);
            ull y2  = 0ull;
#pragma unroll
            for (int j = 0; j < 8; j++) {
                ull Bp = *reinterpret_cast<const ull*>(&Bs[t][2 * j]);
                ull Cp = *reinterpret_cast<const ull*>(&Cs[t][2 * j]);
                h[j] = fma2(h[j], ap, mul2(up, Bp));
                y2   = fma2(h[j], Cp, y2);
                if (j < 7) ap = mul2(ap, e2p);
            }
            float ylo, yhi; upk(y2, ylo, yhi);
            float y = ylo + yhi;
            y = fmaf(xc, Dd, y);
            int u_tok = gmap(dir, g * CH_T + t);
            g_y[((size_t)(n * LSEQ + u_tok)) * DI + d] = y;
        }
    } else {
        float h[DS];
#pragma unroll
        for (int s = 0; s < DS; s++)
            h[s] = g_h0[((size_t)(cg * DS + s)) * DI + d];
        for (int t = 0; t < CH_T; t++) {
            size_t idx = (size_t)(base + t) * DI + d;
            float e, dtv;
            dt_eval(lr[t], Wc, bias, e, dtv);
            float xc = g_xcs[idx];
            float u = dtv * xc;
            float y = 0.f;
#pragma unroll
            for (int s = 0; s < DS; s++) {
                float a = __expf(-dtv * __expf(A_log[d * DS + s]));
                h[s] = fmaf(h[s], a, u * Bs[t][s]);
                y = fmaf(h[s], Cs[t][s], y);
            }
            y = fmaf(xc, Dd, y);
            int u_tok = gmap(dir, g * CH_T + t);
            g_y[((size_t)(n * LSEQ + u_tok)) * DI + d] = y;
        }
    }
}

// ---------------------------------------------------------------------------
// Sum the 4 (already un-permuted) directional y's, multiply by silu(z).
// Pure streaming now.
// ---------------------------------------------------------------------------
__global__ __launch_bounds__(384)
void gather_kernel()
{
    const int u = blockIdx.x, d = threadIdx.x;
    const int b = u >> 12, to = u & 4095;
    float ys = g_y[((size_t)((0 + b) * LSEQ + to)) * DI + d]
             + g_y[((size_t)((2 + b) * LSEQ + to)) * DI + d]
             + g_y[((size_t)((4 + b) * LSEQ + to)) * DI + d]
             + g_y[((size_t)((6 + b) * LSEQ + to)) * DI + d];
    float z  = g_P[((size_t)(b * LSEQ + to)) * 768 + DI + d];
    float sz = z / (1.f + __expf(-z));
    g_G[((size_t)u) * DI + d] = ys * sz;
}

// ---------------------------------------------------------------------------
// LayerNorm over 192 channels
// ---------------------------------------------------------------------------
__global__ __launch_bounds__(192)
void ln_kernel(const float* __restrict__ lg, const float* __restrict__ lb)
{
    const int u = blockIdx.x, j = threadIdx.x;
    float v = g_O1[(size_t)u * DM + j];
    __shared__ float rs[6], rq[6], stats[2];
    float s1 = v, s2 = v * v;
#pragma unroll
    for (int o = 16; o > 0; o >>= 1) {
        s1 += __shfl_down_sync(0xffffffffu, s1, o);
        s2 += __shfl_down_sync(0xffffffffu, s2, o);
    }
    if ((j & 31) == 0) { rs[j >> 5] = s1; rq[j >> 5] = s2; }
    __syncthreads();
    if (j == 0) {
        float a = 0.f, q = 0.f;
        for (int i = 0; i < 6; i++) { a += rs[i]; q += rq[i]; }
        float mu = a * (1.f / DM);
        float var = q * (1.f / DM) - mu * mu;
        stats[0] = mu; stats[1] = rsqrtf(var + 1e-5f);
    }
    __syncthreads();
    g_N1[(size_t)u * DM + j] = (v - stats[0]) * stats[1] * lg[j] + lb[j];
}

// ---------------------------------------------------------------------------
// Launch
// ---------------------------------------------------------------------------
extern "C" void kernel_launch(void* const* d_in, const int* in_sizes, int n_in,
                              void* d_out, int out_size)
{
    const float* x           = (const float*)d_in[0];
    const float* in_proj_w   = (const float*)d_in[1];
    const float* conv_w      = (const float*)d_in[2];
    const float* conv_b      = (const float*)d_in[3];
    const float* x_proj_w    = (const float*)d_in[4];
    const float* dt_proj_w   = (const float*)d_in[5];
    const float* dt_proj_b   = (const float*)d_in[6];
    const float* A_log       = (const float*)d_in[7];
    const float* Dv          = (const float*)d_in[8];
    const float* mamba_out_w = (const float*)d_in[9];
    const float* ln_g        = (const float*)d_in[10];
    const float* ln_b        = (const float*)d_in[11];
    const float* blk_w       = (const float*)d_in[12];
    const float* blk_b       = (const float*)d_in[13];
    float* out = (float*)d_out;

    float *P, *xcs, *dbc, *G, *O1, *N1;
    cudaGetSymbolAddress((void**)&P,   g_P);
    cudaGetSymbolAddress((void**)&xcs, g_xcs);
    cudaGetSymbolAddress((void**)&dbc, g_dbc);
    cudaGetSymbolAddress((void**)&G,   g_G);
    cudaGetSymbolAddress((void**)&O1,  g_O1);
    cudaGetSymbolAddress((void**)&N1,  g_N1);

    // 1) P = x @ in_proj_w              [8192,192]x[192,768]
    gemm_f2<false, false><<<dim3(12, 64), 128>>>(x, in_proj_w, P,
                                                 NTOK, 768, DM, nullptr, nullptr);
    // 2) depthwise conv + SiLU per direction
    conv_kernel<<<dim3(LSEQ, NSEQ), 384>>>(conv_w, conv_b);
    // 3) dbc = xcs @ x_proj_w           [32768,384]x[384,44]
    gemm_f2<true, false><<<dim3(1, 256), 128>>>(xcs, x_proj_w, dbc,
                                                NROWS, 44, DI, nullptr, nullptr);
    // 4-6) chunked selective scan (dt fused into S1/S3)
    scan1_kernel<<<dim3(CH_G, NSEQ), 384>>>(A_log, dt_proj_w, dt_proj_b);
    scan2_kernel<<<dim3(DS, NSEQ), 384>>>(A_log);
    scan3_kernel<<<dim3(CH_G, NSEQ), 384>>>(A_log, Dv, dt_proj_w, dt_proj_b);
    // 7) direction merge * silu(z)  (y already un-permuted)
    gather_kernel<<<NTOK, 384>>>();
    // 8) O1 = G @ mamba_out_w           [8192,384]x[384,192]
    gemm_f2<false, false><<<dim3(3, 64), 128>>>(G, mamba_out_w, O1,
                                                NTOK, DM, DI, nullptr, nullptr);
    // 9) LayerNorm
    ln_kernel<<<NTOK, DM>>>(ln_g, ln_b);
    // 10) out = x + N1 @ blk_w + blk_b
    gemm_f2<false, true><<<dim3(3, 64), 128>>>(N1, blk_w, out,
                                               NTOK, DM, DM, x, blk_b);
    (void)in_sizes; (void)n_in; (void)out_size;
}